// round 1
// baseline (speedup 1.0000x reference)
#include <cuda_runtime.h>
#include <math.h>

#define OUTF 8192
#define INF_ 8192
#define NKCHUNKS 32
#define KCHUNK (INF_ / NKCHUNKS)          // 256
#define T1 256                            // threads per gemm block
#define COLS_PER_THREAD 4
#define COLBLOCKS (OUTF / (T1 * COLS_PER_THREAD))  // 8

// Scratch (no allocations allowed)
__device__ float g_hW[4 * OUTF];
__device__ float g_att[9];

// ---------------------------------------------------------------------------
// Kernel 0: zero the accumulator scratch
// ---------------------------------------------------------------------------
__global__ void zero_kernel() {
    int i = blockIdx.x * blockDim.x + threadIdx.x;
    if (i < 4 * OUTF) g_hW[i] = 0.0f;
}

// ---------------------------------------------------------------------------
// Kernel 1: hW = h[4,8192] @ W[8192,8192]  (split-K, atomic accumulate)
// grid = (COLBLOCKS, NKCHUNKS), block = T1
// Each thread: 4 consecutive output columns, one float4 W load per k.
// ---------------------------------------------------------------------------
__global__ void __launch_bounds__(T1) gemm_kernel(const float* __restrict__ h,
                                                  const float* __restrict__ W) {
    __shared__ float hs[4][KCHUNK];
    const int tid = threadIdx.x;
    const int k0  = blockIdx.y * KCHUNK;

    // Cooperative load of the h chunk (4 x 256 floats)
    for (int i = tid; i < 4 * KCHUNK; i += T1) {
        int m  = i / KCHUNK;
        int kk = i % KCHUNK;
        hs[m][kk] = h[m * INF_ + k0 + kk];
    }
    __syncthreads();

    const int col = (blockIdx.x * T1 + tid) * COLS_PER_THREAD;
    const float4* __restrict__ Wp =
        (const float4*)(W + (size_t)k0 * OUTF + col);
    const int rowstride4 = OUTF / 4;

    float4 a0 = make_float4(0.f, 0.f, 0.f, 0.f);
    float4 a1 = make_float4(0.f, 0.f, 0.f, 0.f);
    float4 a2 = make_float4(0.f, 0.f, 0.f, 0.f);
    float4 a3 = make_float4(0.f, 0.f, 0.f, 0.f);

#pragma unroll 4
    for (int kk = 0; kk < KCHUNK; kk++) {
        float4 w = Wp[(size_t)kk * rowstride4];
        float h0 = hs[0][kk], h1 = hs[1][kk], h2 = hs[2][kk], h3 = hs[3][kk];
        a0.x += h0 * w.x; a0.y += h0 * w.y; a0.z += h0 * w.z; a0.w += h0 * w.w;
        a1.x += h1 * w.x; a1.y += h1 * w.y; a1.z += h1 * w.z; a1.w += h1 * w.w;
        a2.x += h2 * w.x; a2.y += h2 * w.y; a2.z += h2 * w.z; a2.w += h2 * w.w;
        a3.x += h3 * w.x; a3.y += h3 * w.y; a3.z += h3 * w.z; a3.w += h3 * w.w;
    }

    atomicAdd(&g_hW[0 * OUTF + col + 0], a0.x);
    atomicAdd(&g_hW[0 * OUTF + col + 1], a0.y);
    atomicAdd(&g_hW[0 * OUTF + col + 2], a0.z);
    atomicAdd(&g_hW[0 * OUTF + col + 3], a0.w);
    atomicAdd(&g_hW[1 * OUTF + col + 0], a1.x);
    atomicAdd(&g_hW[1 * OUTF + col + 1], a1.y);
    atomicAdd(&g_hW[1 * OUTF + col + 2], a1.z);
    atomicAdd(&g_hW[1 * OUTF + col + 3], a1.w);
    atomicAdd(&g_hW[2 * OUTF + col + 0], a2.x);
    atomicAdd(&g_hW[2 * OUTF + col + 1], a2.y);
    atomicAdd(&g_hW[2 * OUTF + col + 2], a2.z);
    atomicAdd(&g_hW[2 * OUTF + col + 3], a2.w);
    atomicAdd(&g_hW[3 * OUTF + col + 0], a3.x);
    atomicAdd(&g_hW[3 * OUTF + col + 1], a3.y);
    atomicAdd(&g_hW[3 * OUTF + col + 2], a3.z);
    atomicAdd(&g_hW[3 * OUTF + col + 3], a3.w);
}

// ---------------------------------------------------------------------------
// Kernel 2: pairwise distances -> e -> attention (3x3 softmax over axis 0)
// One block, 1024 threads. Writes g_att and the 3 scalar outputs.
// ---------------------------------------------------------------------------
__global__ void __launch_bounds__(1024) attn_kernel(const int* __restrict__ adj,
                                                    float* __restrict__ out,
                                                    int out_size) {
    __shared__ float red[6][32];
    const int tid = threadIdx.x;

    float s01 = 0.f, s02 = 0.f, s03 = 0.f, s12 = 0.f, s13 = 0.f, s23 = 0.f;
    for (int k = tid; k < OUTF; k += 1024) {
        float x0 = g_hW[0 * OUTF + k];
        float x1 = g_hW[1 * OUTF + k];
        float x2 = g_hW[2 * OUTF + k];
        float x3 = g_hW[3 * OUTF + k];
        float d;
        d = x0 - x1; s01 += d * d;
        d = x0 - x2; s02 += d * d;
        d = x0 - x3; s03 += d * d;
        d = x1 - x2; s12 += d * d;
        d = x1 - x3; s13 += d * d;
        d = x2 - x3; s23 += d * d;
    }
#pragma unroll
    for (int off = 16; off > 0; off >>= 1) {
        s01 += __shfl_down_sync(0xffffffffu, s01, off);
        s02 += __shfl_down_sync(0xffffffffu, s02, off);
        s03 += __shfl_down_sync(0xffffffffu, s03, off);
        s12 += __shfl_down_sync(0xffffffffu, s12, off);
        s13 += __shfl_down_sync(0xffffffffu, s13, off);
        s23 += __shfl_down_sync(0xffffffffu, s23, off);
    }
    int w = tid >> 5, l = tid & 31;
    if (l == 0) {
        red[0][w] = s01; red[1][w] = s02; red[2][w] = s03;
        red[3][w] = s12; red[4][w] = s13; red[5][w] = s23;
    }
    __syncthreads();

    if (tid == 0) {
        float t[6] = {0.f, 0.f, 0.f, 0.f, 0.f, 0.f};
        for (int i = 0; i < 32; i++) {
            t[0] += red[0][i]; t[1] += red[1][i]; t[2] += red[2][i];
            t[3] += red[3][i]; t[4] += red[4][i]; t[5] += red[5][i];
        }
        // zero-safe sqrt (matches reference _cdist)
        float d01 = (t[0] > 0.f) ? sqrtf(t[0]) : 0.f;
        float d02 = (t[1] > 0.f) ? sqrtf(t[1]) : 0.f;
        float d03 = (t[2] > 0.f) ? sqrtf(t[2]) : 0.f;
        float d12 = (t[3] > 0.f) ? sqrtf(t[3]) : 0.f;
        float d13 = (t[4] > 0.f) ? sqrtf(t[4]) : 0.f;
        float d23 = (t[5] > 0.f) ? sqrtf(t[5]) : 0.f;
        // leaky_relu is identity for x >= 0 (distances are nonnegative)
        float v01 = d12 + 0.5f * (d01 + d02);   // e2[1,2] + (e2[0,1]+e2[0,2])/2
        float v02 = d13 + 0.5f * (d01 + d03);
        float v12 = d23 + 0.5f * (d02 + d03);

        float e[3][3] = {{0.f, v01, v02},
                         {v01, 0.f, v12},
                         {v02, v12, 0.f}};

        // softmax over axis 0 (per column), with adj mask
        for (int j = 0; j < 3; j++) {
            float c[3];
            for (int i = 0; i < 3; i++)
                c[i] = (adj[i * 3 + j] > 0) ? e[i][j] : -9e15f;
            float mx = fmaxf(c[0], fmaxf(c[1], c[2]));
            float ex0 = expf(c[0] - mx);
            float ex1 = expf(c[1] - mx);
            float ex2 = expf(c[2] - mx);
            float inv = 1.0f / (ex0 + ex1 + ex2);
            g_att[0 * 3 + j] = ex0 * inv;
            g_att[1 * 3 + j] = ex1 * inv;
            g_att[2 * 3 + j] = ex2 * inv;
        }
        // scalar outputs: face_Rhand, face_Lhand, Rhand_Lhand
        out[out_size - 3] = v01;
        out[out_size - 2] = v02;
        out[out_size - 1] = v12;
    }
}

// ---------------------------------------------------------------------------
// Kernel 3: h_prime = attention @ hW[1:4]; assemble output rows
// ---------------------------------------------------------------------------
__global__ void __launch_bounds__(256) hprime_kernel(float* __restrict__ out) {
    __shared__ float att[9];
    if (threadIdx.x < 9) att[threadIdx.x] = g_att[threadIdx.x];
    __syncthreads();

    for (int c = blockIdx.x * blockDim.x + threadIdx.x; c < OUTF;
         c += gridDim.x * blockDim.x) {
        float b0 = g_hW[1 * OUTF + c];
        float b1 = g_hW[2 * OUTF + c];
        float b2 = g_hW[3 * OUTF + c];
        out[c] = g_hW[c];  // row 0 is h[0] after projection
        out[1 * OUTF + c] = att[0] * b0 + att[1] * b1 + att[2] * b2;
        out[2 * OUTF + c] = att[3] * b0 + att[4] * b1 + att[5] * b2;
        out[3 * OUTF + c] = att[6] * b0 + att[7] * b1 + att[8] * b2;
    }
}

// ---------------------------------------------------------------------------
extern "C" void kernel_launch(void* const* d_in, const int* in_sizes, int n_in,
                              void* d_out, int out_size) {
    const float* h   = (const float*)d_in[0];   // [4, 8192]
    const int*   adj = (const int*)d_in[1];     // [3, 3]
    const float* W   = (const float*)d_in[2];   // [8192, 8192]
    float* out = (float*)d_out;

    zero_kernel<<<(4 * OUTF + 255) / 256, 256>>>();

    dim3 g1(COLBLOCKS, NKCHUNKS);
    gemm_kernel<<<g1, T1>>>(h, W);

    attn_kernel<<<1, 1024>>>(adj, out, out_size);

    hprime_kernel<<<32, 256>>>(out);
}

// round 2
// speedup vs baseline: 1.4008x; 1.4008x over previous
#include <cuda_runtime.h>
#include <math.h>

#define OUTF 8192
#define INF_ 8192
#define NKCHUNKS 128
#define KCHUNK (INF_ / NKCHUNKS)          // 64
#define T1 256                            // threads per gemm block
#define COLS_PER_THREAD 4
#define COLBLOCKS (OUTF / (T1 * COLS_PER_THREAD))  // 8

// Scratch (no allocations allowed)
__device__ float g_hW[4 * OUTF];
__device__ float g_att[9];

// ---------------------------------------------------------------------------
// Kernel 0: zero the accumulator scratch (float4)
// ---------------------------------------------------------------------------
__global__ void zero_kernel() {
    int i = blockIdx.x * blockDim.x + threadIdx.x;
    if (i < OUTF) ((float4*)g_hW)[i] = make_float4(0.f, 0.f, 0.f, 0.f);
}

// ---------------------------------------------------------------------------
// Kernel 1: hW = h[4,8192] @ W[8192,8192]  (split-K, atomic accumulate)
// grid = (COLBLOCKS, NKCHUNKS) = (8, 128), block = 256
// Each thread: 4 consecutive output columns, one float4 W load per k.
// ---------------------------------------------------------------------------
__global__ void __launch_bounds__(T1, 4) gemm_kernel(const float* __restrict__ h,
                                                     const float* __restrict__ W) {
    __shared__ float hs[4][KCHUNK];
    const int tid = threadIdx.x;
    const int k0  = blockIdx.y * KCHUNK;

    // Cooperative load of the h chunk (4 x 64 floats)
    if (tid < 4 * KCHUNK) {
        int m  = tid / KCHUNK;
        int kk = tid % KCHUNK;
        hs[m][kk] = h[m * INF_ + k0 + kk];
    }
    __syncthreads();

    const int col = (blockIdx.x * T1 + tid) * COLS_PER_THREAD;
    const float4* __restrict__ Wp =
        (const float4*)(W + (size_t)k0 * OUTF + col);
    const int rowstride4 = OUTF / 4;

    float4 a0 = make_float4(0.f, 0.f, 0.f, 0.f);
    float4 a1 = make_float4(0.f, 0.f, 0.f, 0.f);
    float4 a2 = make_float4(0.f, 0.f, 0.f, 0.f);
    float4 a3 = make_float4(0.f, 0.f, 0.f, 0.f);

#pragma unroll 8
    for (int kk = 0; kk < KCHUNK; kk++) {
        float4 w = Wp[(size_t)kk * rowstride4];
        float h0 = hs[0][kk], h1 = hs[1][kk], h2 = hs[2][kk], h3 = hs[3][kk];
        a0.x += h0 * w.x; a0.y += h0 * w.y; a0.z += h0 * w.z; a0.w += h0 * w.w;
        a1.x += h1 * w.x; a1.y += h1 * w.y; a1.z += h1 * w.z; a1.w += h1 * w.w;
        a2.x += h2 * w.x; a2.y += h2 * w.y; a2.z += h2 * w.z; a2.w += h2 * w.w;
        a3.x += h3 * w.x; a3.y += h3 * w.y; a3.z += h3 * w.z; a3.w += h3 * w.w;
    }

    atomicAdd(&g_hW[0 * OUTF + col + 0], a0.x);
    atomicAdd(&g_hW[0 * OUTF + col + 1], a0.y);
    atomicAdd(&g_hW[0 * OUTF + col + 2], a0.z);
    atomicAdd(&g_hW[0 * OUTF + col + 3], a0.w);
    atomicAdd(&g_hW[1 * OUTF + col + 0], a1.x);
    atomicAdd(&g_hW[1 * OUTF + col + 1], a1.y);
    atomicAdd(&g_hW[1 * OUTF + col + 2], a1.z);
    atomicAdd(&g_hW[1 * OUTF + col + 3], a1.w);
    atomicAdd(&g_hW[2 * OUTF + col + 0], a2.x);
    atomicAdd(&g_hW[2 * OUTF + col + 1], a2.y);
    atomicAdd(&g_hW[2 * OUTF + col + 2], a2.z);
    atomicAdd(&g_hW[2 * OUTF + col + 3], a2.w);
    atomicAdd(&g_hW[3 * OUTF + col + 0], a3.x);
    atomicAdd(&g_hW[3 * OUTF + col + 1], a3.y);
    atomicAdd(&g_hW[3 * OUTF + col + 2], a3.z);
    atomicAdd(&g_hW[3 * OUTF + col + 3], a3.w);
}

// ---------------------------------------------------------------------------
// Kernel 2: pairwise distances -> e -> attention (3x3 softmax over axis 0)
// One block, 1024 threads. Writes g_att and the 3 scalar outputs.
// ---------------------------------------------------------------------------
__global__ void __launch_bounds__(1024) attn_kernel(const int* __restrict__ adj,
                                                    float* __restrict__ out,
                                                    int out_size) {
    __shared__ float red[6][32];
    const int tid = threadIdx.x;

    float s01 = 0.f, s02 = 0.f, s03 = 0.f, s12 = 0.f, s13 = 0.f, s23 = 0.f;
    for (int k = tid; k < OUTF / 4; k += 1024) {
        float4 x0 = ((const float4*)g_hW)[0 * OUTF / 4 + k];
        float4 x1 = ((const float4*)g_hW)[1 * OUTF / 4 + k];
        float4 x2 = ((const float4*)g_hW)[2 * OUTF / 4 + k];
        float4 x3 = ((const float4*)g_hW)[3 * OUTF / 4 + k];
        float d;
        d = x0.x - x1.x; s01 += d * d; d = x0.y - x1.y; s01 += d * d;
        d = x0.z - x1.z; s01 += d * d; d = x0.w - x1.w; s01 += d * d;
        d = x0.x - x2.x; s02 += d * d; d = x0.y - x2.y; s02 += d * d;
        d = x0.z - x2.z; s02 += d * d; d = x0.w - x2.w; s02 += d * d;
        d = x0.x - x3.x; s03 += d * d; d = x0.y - x3.y; s03 += d * d;
        d = x0.z - x3.z; s03 += d * d; d = x0.w - x3.w; s03 += d * d;
        d = x1.x - x2.x; s12 += d * d; d = x1.y - x2.y; s12 += d * d;
        d = x1.z - x2.z; s12 += d * d; d = x1.w - x2.w; s12 += d * d;
        d = x1.x - x3.x; s13 += d * d; d = x1.y - x3.y; s13 += d * d;
        d = x1.z - x3.z; s13 += d * d; d = x1.w - x3.w; s13 += d * d;
        d = x2.x - x3.x; s23 += d * d; d = x2.y - x3.y; s23 += d * d;
        d = x2.z - x3.z; s23 += d * d; d = x2.w - x3.w; s23 += d * d;
    }
#pragma unroll
    for (int off = 16; off > 0; off >>= 1) {
        s01 += __shfl_down_sync(0xffffffffu, s01, off);
        s02 += __shfl_down_sync(0xffffffffu, s02, off);
        s03 += __shfl_down_sync(0xffffffffu, s03, off);
        s12 += __shfl_down_sync(0xffffffffu, s12, off);
        s13 += __shfl_down_sync(0xffffffffu, s13, off);
        s23 += __shfl_down_sync(0xffffffffu, s23, off);
    }
    int w = tid >> 5, l = tid & 31;
    if (l == 0) {
        red[0][w] = s01; red[1][w] = s02; red[2][w] = s03;
        red[3][w] = s12; red[4][w] = s13; red[5][w] = s23;
    }
    __syncthreads();

    if (tid == 0) {
        float t[6] = {0.f, 0.f, 0.f, 0.f, 0.f, 0.f};
        for (int i = 0; i < 32; i++) {
            t[0] += red[0][i]; t[1] += red[1][i]; t[2] += red[2][i];
            t[3] += red[3][i]; t[4] += red[4][i]; t[5] += red[5][i];
        }
        // zero-safe sqrt (matches reference _cdist)
        float d01 = (t[0] > 0.f) ? sqrtf(t[0]) : 0.f;
        float d02 = (t[1] > 0.f) ? sqrtf(t[1]) : 0.f;
        float d03 = (t[2] > 0.f) ? sqrtf(t[2]) : 0.f;
        float d12 = (t[3] > 0.f) ? sqrtf(t[3]) : 0.f;
        float d13 = (t[4] > 0.f) ? sqrtf(t[4]) : 0.f;
        float d23 = (t[5] > 0.f) ? sqrtf(t[5]) : 0.f;
        // leaky_relu is identity for x >= 0 (distances are nonnegative)
        float v01 = d12 + 0.5f * (d01 + d02);   // e2[1,2] + (e2[0,1]+e2[0,2])/2
        float v02 = d13 + 0.5f * (d01 + d03);
        float v12 = d23 + 0.5f * (d02 + d03);

        float e[3][3] = {{0.f, v01, v02},
                         {v01, 0.f, v12},
                         {v02, v12, 0.f}};

        // softmax over axis 0 (per column), with adj mask
        for (int j = 0; j < 3; j++) {
            float c[3];
            for (int i = 0; i < 3; i++)
                c[i] = (adj[i * 3 + j] > 0) ? e[i][j] : -9e15f;
            float mx = fmaxf(c[0], fmaxf(c[1], c[2]));
            float ex0 = expf(c[0] - mx);
            float ex1 = expf(c[1] - mx);
            float ex2 = expf(c[2] - mx);
            float inv = 1.0f / (ex0 + ex1 + ex2);
            g_att[0 * 3 + j] = ex0 * inv;
            g_att[1 * 3 + j] = ex1 * inv;
            g_att[2 * 3 + j] = ex2 * inv;
        }
        // scalar outputs: face_Rhand, face_Lhand, Rhand_Lhand
        out[out_size - 3] = v01;
        out[out_size - 2] = v02;
        out[out_size - 1] = v12;
    }
}

// ---------------------------------------------------------------------------
// Kernel 3: h_prime = attention @ hW[1:4]; assemble output rows (float4)
// ---------------------------------------------------------------------------
__global__ void __launch_bounds__(256) hprime_kernel(float* __restrict__ out) {
    __shared__ float att[9];
    if (threadIdx.x < 9) att[threadIdx.x] = g_att[threadIdx.x];
    __syncthreads();

    const float4* hw = (const float4*)g_hW;
    float4* o = (float4*)out;
    const int N4 = OUTF / 4;

    for (int c = blockIdx.x * blockDim.x + threadIdx.x; c < N4;
         c += gridDim.x * blockDim.x) {
        float4 b0 = hw[1 * N4 + c];
        float4 b1 = hw[2 * N4 + c];
        float4 b2 = hw[3 * N4 + c];
        o[c] = hw[c];  // row 0 is h[0] after projection
        float4 r;
        r.x = att[0] * b0.x + att[1] * b1.x + att[2] * b2.x;
        r.y = att[0] * b0.y + att[1] * b1.y + att[2] * b2.y;
        r.z = att[0] * b0.z + att[1] * b1.z + att[2] * b2.z;
        r.w = att[0] * b0.w + att[1] * b1.w + att[2] * b2.w;
        o[1 * N4 + c] = r;
        r.x = att[3] * b0.x + att[4] * b1.x + att[5] * b2.x;
        r.y = att[3] * b0.y + att[4] * b1.y + att[5] * b2.y;
        r.z = att[3] * b0.z + att[4] * b1.z + att[5] * b2.z;
        r.w = att[3] * b0.w + att[4] * b1.w + att[5] * b2.w;
        o[2 * N4 + c] = r;
        r.x = att[6] * b0.x + att[7] * b1.x + att[8] * b2.x;
        r.y = att[6] * b0.y + att[7] * b1.y + att[8] * b2.y;
        r.z = att[6] * b0.z + att[7] * b1.z + att[8] * b2.z;
        r.w = att[6] * b0.w + att[7] * b1.w + att[8] * b2.w;
        o[3 * N4 + c] = r;
    }
}

// ---------------------------------------------------------------------------
extern "C" void kernel_launch(void* const* d_in, const int* in_sizes, int n_in,
                              void* d_out, int out_size) {
    const float* h   = (const float*)d_in[0];   // [4, 8192]
    const int*   adj = (const int*)d_in[1];     // [3, 3]
    const float* W   = (const float*)d_in[2];   // [8192, 8192]
    float* out = (float*)d_out;

    zero_kernel<<<(OUTF + 255) / 256, 256>>>();

    dim3 g1(COLBLOCKS, NKCHUNKS);
    gemm_kernel<<<g1, T1>>>(h, W);

    attn_kernel<<<1, 1024>>>(adj, out, out_size);

    hprime_kernel<<<64, 256>>>(out);
}

// round 3
// speedup vs baseline: 1.4612x; 1.0431x over previous
#include <cuda_runtime.h>
#include <math.h>

#define OUTF 8192
#define INF_ 8192
#define NKCHUNKS 64
#define KCHUNK (INF_ / NKCHUNKS)          // 128
#define T1 256                            // threads per gemm block
#define COLS_PER_THREAD 4
#define COLBLOCKS (OUTF / (T1 * COLS_PER_THREAD))  // 8  -> grid 8*64=512 (single wave)

// Scratch (no allocations allowed)
__device__ float g_hW[4 * OUTF];

// ---------------------------------------------------------------------------
// Kernel 0: zero the accumulator scratch (float4)
// ---------------------------------------------------------------------------
__global__ void zero_kernel() {
    int i = blockIdx.x * blockDim.x + threadIdx.x;
    if (i < OUTF) ((float4*)g_hW)[i] = make_float4(0.f, 0.f, 0.f, 0.f);
}

// ---------------------------------------------------------------------------
// Kernel 1: hW = h[4,8192] @ W[8192,8192]  (split-K, atomic accumulate)
// grid = (8, 64) = 512 blocks -> one wave at occ>=4, block = 256
// Each thread: 4 consecutive output columns, one float4 W load per k.
// ---------------------------------------------------------------------------
__global__ void __launch_bounds__(T1, 4) gemm_kernel(const float* __restrict__ h,
                                                     const float* __restrict__ W) {
    __shared__ float hs[4][KCHUNK];
    const int tid = threadIdx.x;
    const int k0  = blockIdx.y * KCHUNK;

    // Cooperative load of the h chunk (4 x 128 floats)
    for (int i = tid; i < 4 * KCHUNK; i += T1) {
        int m  = i / KCHUNK;
        int kk = i % KCHUNK;
        hs[m][kk] = h[m * INF_ + k0 + kk];
    }
    __syncthreads();

    const int col = (blockIdx.x * T1 + tid) * COLS_PER_THREAD;
    const float4* __restrict__ Wp =
        (const float4*)(W + (size_t)k0 * OUTF + col);
    const int rowstride4 = OUTF / 4;

    float4 a0 = make_float4(0.f, 0.f, 0.f, 0.f);
    float4 a1 = make_float4(0.f, 0.f, 0.f, 0.f);
    float4 a2 = make_float4(0.f, 0.f, 0.f, 0.f);
    float4 a3 = make_float4(0.f, 0.f, 0.f, 0.f);

#pragma unroll 8
    for (int kk = 0; kk < KCHUNK; kk++) {
        float4 w = Wp[(size_t)kk * rowstride4];
        float h0 = hs[0][kk], h1 = hs[1][kk], h2 = hs[2][kk], h3 = hs[3][kk];
        a0.x += h0 * w.x; a0.y += h0 * w.y; a0.z += h0 * w.z; a0.w += h0 * w.w;
        a1.x += h1 * w.x; a1.y += h1 * w.y; a1.z += h1 * w.z; a1.w += h1 * w.w;
        a2.x += h2 * w.x; a2.y += h2 * w.y; a2.z += h2 * w.z; a2.w += h2 * w.w;
        a3.x += h3 * w.x; a3.y += h3 * w.y; a3.z += h3 * w.z; a3.w += h3 * w.w;
    }

    atomicAdd(&g_hW[0 * OUTF + col + 0], a0.x);
    atomicAdd(&g_hW[0 * OUTF + col + 1], a0.y);
    atomicAdd(&g_hW[0 * OUTF + col + 2], a0.z);
    atomicAdd(&g_hW[0 * OUTF + col + 3], a0.w);
    atomicAdd(&g_hW[1 * OUTF + col + 0], a1.x);
    atomicAdd(&g_hW[1 * OUTF + col + 1], a1.y);
    atomicAdd(&g_hW[1 * OUTF + col + 2], a1.z);
    atomicAdd(&g_hW[1 * OUTF + col + 3], a1.w);
    atomicAdd(&g_hW[2 * OUTF + col + 0], a2.x);
    atomicAdd(&g_hW[2 * OUTF + col + 1], a2.y);
    atomicAdd(&g_hW[2 * OUTF + col + 2], a2.z);
    atomicAdd(&g_hW[2 * OUTF + col + 3], a2.w);
    atomicAdd(&g_hW[3 * OUTF + col + 0], a3.x);
    atomicAdd(&g_hW[3 * OUTF + col + 1], a3.y);
    atomicAdd(&g_hW[3 * OUTF + col + 2], a3.z);
    atomicAdd(&g_hW[3 * OUTF + col + 3], a3.w);
}

// ---------------------------------------------------------------------------
// Kernel 2 (fused): distances -> attention (3x3 softmax over axis 0)
//                   -> h_prime = attention @ hW[1:] -> full output assembly
// One block, 1024 threads.
// ---------------------------------------------------------------------------
__global__ void __launch_bounds__(1024) attn_hprime_kernel(const int* __restrict__ adj,
                                                           float* __restrict__ out,
                                                           int out_size) {
    __shared__ float red[6][32];
    __shared__ float att_s[9];
    const int tid = threadIdx.x;

    float s01 = 0.f, s02 = 0.f, s03 = 0.f, s12 = 0.f, s13 = 0.f, s23 = 0.f;
    for (int k = tid; k < OUTF / 4; k += 1024) {
        float4 x0 = ((const float4*)g_hW)[0 * OUTF / 4 + k];
        float4 x1 = ((const float4*)g_hW)[1 * OUTF / 4 + k];
        float4 x2 = ((const float4*)g_hW)[2 * OUTF / 4 + k];
        float4 x3 = ((const float4*)g_hW)[3 * OUTF / 4 + k];
        float d;
        d = x0.x - x1.x; s01 += d * d; d = x0.y - x1.y; s01 += d * d;
        d = x0.z - x1.z; s01 += d * d; d = x0.w - x1.w; s01 += d * d;
        d = x0.x - x2.x; s02 += d * d; d = x0.y - x2.y; s02 += d * d;
        d = x0.z - x2.z; s02 += d * d; d = x0.w - x2.w; s02 += d * d;
        d = x0.x - x3.x; s03 += d * d; d = x0.y - x3.y; s03 += d * d;
        d = x0.z - x3.z; s03 += d * d; d = x0.w - x3.w; s03 += d * d;
        d = x1.x - x2.x; s12 += d * d; d = x1.y - x2.y; s12 += d * d;
        d = x1.z - x2.z; s12 += d * d; d = x1.w - x2.w; s12 += d * d;
        d = x1.x - x3.x; s13 += d * d; d = x1.y - x3.y; s13 += d * d;
        d = x1.z - x3.z; s13 += d * d; d = x1.w - x3.w; s13 += d * d;
        d = x2.x - x3.x; s23 += d * d; d = x2.y - x3.y; s23 += d * d;
        d = x2.z - x3.z; s23 += d * d; d = x2.w - x3.w; s23 += d * d;
    }
#pragma unroll
    for (int off = 16; off > 0; off >>= 1) {
        s01 += __shfl_down_sync(0xffffffffu, s01, off);
        s02 += __shfl_down_sync(0xffffffffu, s02, off);
        s03 += __shfl_down_sync(0xffffffffu, s03, off);
        s12 += __shfl_down_sync(0xffffffffu, s12, off);
        s13 += __shfl_down_sync(0xffffffffu, s13, off);
        s23 += __shfl_down_sync(0xffffffffu, s23, off);
    }
    int w = tid >> 5, l = tid & 31;
    if (l == 0) {
        red[0][w] = s01; red[1][w] = s02; red[2][w] = s03;
        red[3][w] = s12; red[4][w] = s13; red[5][w] = s23;
    }
    __syncthreads();

    if (tid == 0) {
        float t[6] = {0.f, 0.f, 0.f, 0.f, 0.f, 0.f};
        for (int i = 0; i < 32; i++) {
            t[0] += red[0][i]; t[1] += red[1][i]; t[2] += red[2][i];
            t[3] += red[3][i]; t[4] += red[4][i]; t[5] += red[5][i];
        }
        // zero-safe sqrt (matches reference _cdist)
        float d01 = (t[0] > 0.f) ? sqrtf(t[0]) : 0.f;
        float d02 = (t[1] > 0.f) ? sqrtf(t[1]) : 0.f;
        float d03 = (t[2] > 0.f) ? sqrtf(t[2]) : 0.f;
        float d12 = (t[3] > 0.f) ? sqrtf(t[3]) : 0.f;
        float d13 = (t[4] > 0.f) ? sqrtf(t[4]) : 0.f;
        float d23 = (t[5] > 0.f) ? sqrtf(t[5]) : 0.f;
        // leaky_relu is identity for x >= 0 (distances are nonnegative)
        float v01 = d12 + 0.5f * (d01 + d02);   // e2[1,2] + (e2[0,1]+e2[0,2])/2
        float v02 = d13 + 0.5f * (d01 + d03);
        float v12 = d23 + 0.5f * (d02 + d03);

        float e[3][3] = {{0.f, v01, v02},
                         {v01, 0.f, v12},
                         {v02, v12, 0.f}};

        // softmax over axis 0 (per column), with adj mask
        for (int j = 0; j < 3; j++) {
            float c[3];
            for (int i = 0; i < 3; i++)
                c[i] = (adj[i * 3 + j] > 0) ? e[i][j] : -9e15f;
            float mx = fmaxf(c[0], fmaxf(c[1], c[2]));
            float ex0 = expf(c[0] - mx);
            float ex1 = expf(c[1] - mx);
            float ex2 = expf(c[2] - mx);
            float inv = 1.0f / (ex0 + ex1 + ex2);
            att_s[0 * 3 + j] = ex0 * inv;
            att_s[1 * 3 + j] = ex1 * inv;
            att_s[2 * 3 + j] = ex2 * inv;
        }
        // scalar outputs: face_Rhand, face_Lhand, Rhand_Lhand
        out[out_size - 3] = v01;
        out[out_size - 2] = v02;
        out[out_size - 1] = v12;
    }
    __syncthreads();

    // h_prime = attention @ hW[1:4]; row 0 is hW[0]. (float4, 2 iters/thread)
    const float a00 = att_s[0], a01 = att_s[1], a02 = att_s[2];
    const float a10 = att_s[3], a11 = att_s[4], a12 = att_s[5];
    const float a20 = att_s[6], a21 = att_s[7], a22 = att_s[8];
    const float4* hw = (const float4*)g_hW;
    float4* o = (float4*)out;
    const int N4 = OUTF / 4;

    for (int c = tid; c < N4; c += 1024) {
        float4 b0 = hw[1 * N4 + c];
        float4 b1 = hw[2 * N4 + c];
        float4 b2 = hw[3 * N4 + c];
        o[c] = hw[c];
        float4 r;
        r.x = a00 * b0.x + a01 * b1.x + a02 * b2.x;
        r.y = a00 * b0.y + a01 * b1.y + a02 * b2.y;
        r.z = a00 * b0.z + a01 * b1.z + a02 * b2.z;
        r.w = a00 * b0.w + a01 * b1.w + a02 * b2.w;
        o[1 * N4 + c] = r;
        r.x = a10 * b0.x + a11 * b1.x + a12 * b2.x;
        r.y = a10 * b0.y + a11 * b1.y + a12 * b2.y;
        r.z = a10 * b0.z + a11 * b1.z + a12 * b2.z;
        r.w = a10 * b0.w + a11 * b1.w + a12 * b2.w;
        o[2 * N4 + c] = r;
        r.x = a20 * b0.x + a21 * b1.x + a22 * b2.x;
        r.y = a20 * b0.y + a21 * b1.y + a22 * b2.y;
        r.z = a20 * b0.z + a21 * b1.z + a22 * b2.z;
        r.w = a20 * b0.w + a21 * b1.w + a22 * b2.w;
        o[3 * N4 + c] = r;
    }
}

// ---------------------------------------------------------------------------
extern "C" void kernel_launch(void* const* d_in, const int* in_sizes, int n_in,
                              void* d_out, int out_size) {
    const float* h   = (const float*)d_in[0];   // [4, 8192]
    const int*   adj = (const int*)d_in[1];     // [3, 3]
    const float* W   = (const float*)d_in[2];   // [8192, 8192]
    float* out = (float*)d_out;

    zero_kernel<<<(OUTF + 255) / 256, 256>>>();

    dim3 g1(COLBLOCKS, NKCHUNKS);
    gemm_kernel<<<g1, T1>>>(h, W);

    attn_hprime_kernel<<<1, 1024>>>(adj, out, out_size);
}